// round 1
// baseline (speedup 1.0000x reference)
#include <cuda_runtime.h>
#include <cstdint>

namespace {
constexpr int Bc = 8, Hc = 16, Sc = 1024, Dc = 64;
constexpr int BH = Bc * Hc;
constexpr int TQ = 32;            // q rows per CTA
constexpr int NT = 256;           // threads per CTA
constexpr int KT = 64;            // k tile
// smem pitches (floats), chosen for conflict-free mma fragment LDS
constexpr int SQ_P = 68;
constexpr int SK_P = 68;
constexpr int SV_P = 72;
constexpr int SS_P = 1028;
constexpr int SMEM_FLOATS = TQ * SS_P + TQ * SQ_P + KT * SK_P + KT * SV_P;
constexpr size_t ATTN_OFF = (size_t)BH * Sc * Dc;   // out first, then attn
}

__device__ __forceinline__ float to_tf32(float x) {
    uint32_t u;
    asm("cvt.rna.tf32.f32 %0, %1;" : "=r"(u) : "f"(x));
    return __uint_as_float(u);
}

__device__ __forceinline__ void mma8(float c[4],
                                     float a0, float a1, float a2, float a3,
                                     float b0, float b1) {
    asm volatile(
        "mma.sync.aligned.m16n8k8.row.col.f32.tf32.tf32.f32 "
        "{%0,%1,%2,%3}, {%4,%5,%6,%7}, {%8,%9}, {%0,%1,%2,%3};\n"
        : "+f"(c[0]), "+f"(c[1]), "+f"(c[2]), "+f"(c[3])
        : "r"(__float_as_uint(a0)), "r"(__float_as_uint(a1)),
          "r"(__float_as_uint(a2)), "r"(__float_as_uint(a3)),
          "r"(__float_as_uint(b0)), "r"(__float_as_uint(b1)));
}

__global__ void __launch_bounds__(NT, 1)
attn_tf32_kernel(const float* __restrict__ Qg_, const float* __restrict__ Kg_,
                 const float* __restrict__ Vg_, const int* __restrict__ Mg_,
                 float* __restrict__ out)
{
    extern __shared__ float sm[];
    float* sS = sm;                       // [TQ][SS_P]  scores / exp / tf32(attn)
    float* sQ = sS + TQ * SS_P;           // [TQ][SQ_P]  tf32(Q/8)
    float* sK = sQ + TQ * SQ_P;           // [KT][SK_P]  tf32(K tile)
    float* sV = sK + KT * SK_P;           // [KT][SV_P]  tf32(V tile)

    const int qt   = blockIdx.x;          // 0..31
    const int bh   = blockIdx.y;          // 0..127
    const int b    = bh >> 4;
    const int tid  = threadIdx.x;
    const int warp = tid >> 5;
    const int lane = tid & 31;
    const int gid  = lane >> 2;           // 0..7
    const int tig  = lane & 3;            // 0..3

    const float* Qg = Qg_ + ((size_t)bh * Sc + (size_t)qt * TQ) * Dc;
    const float* Kg = Kg_ + (size_t)bh * Sc * Dc;
    const float* Vg = Vg_ + (size_t)bh * Sc * Dc;
    float* outO = out + ((size_t)bh * Sc + (size_t)qt * TQ) * Dc;
    float* outA = out + ATTN_OFF + ((size_t)bh * Sc + (size_t)qt * TQ) * Sc;
    const int* Mg = Mg_ + ((size_t)b * Sc + (size_t)qt * TQ) * Sc;

    // ---------------- load Q tile: scale by 1/sqrt(D)=0.125, round to tf32 ----
    for (int i = tid; i < TQ * Dc / 4; i += NT) {
        int row = i >> 4, c4 = i & 15;
        float4 v = reinterpret_cast<const float4*>(Qg)[i];
        float* dst = sQ + row * SQ_P + c4 * 4;
        dst[0] = to_tf32(v.x * 0.125f);
        dst[1] = to_tf32(v.y * 0.125f);
        dst[2] = to_tf32(v.z * 0.125f);
        dst[3] = to_tf32(v.w * 0.125f);
    }
    __syncthreads();

    // Warp tiling: q-half (16 rows) x quarter (16 cols of the 64-wide tile)
    const int qb = (warp >> 2) << 4;      // 0 or 16
    const int kq = (warp & 3) << 4;       // 0,16,32,48

    // Preload A fragments (Q) once: reused across all 16 K tiles.
    float aq[8][4];
#pragma unroll
    for (int ks = 0; ks < 8; ks++) {
        const float* p = sQ + (qb + gid) * SQ_P + ks * 8 + tig;
        aq[ks][0] = p[0];
        aq[ks][1] = p[8 * SQ_P];
        aq[ks][2] = p[4];
        aq[ks][3] = p[8 * SQ_P + 4];
    }

    // ---------------- GEMM1: scores = (Q/8) @ K^T ----------------------------
    for (int kt = 0; kt < Sc / KT; kt++) {
        __syncthreads();   // prior mma reads of sK complete before overwrite
        for (int i = tid; i < KT * Dc / 4; i += NT) {
            int row = i >> 4, c4 = i & 15;
            float4 v = reinterpret_cast<const float4*>(Kg + kt * KT * Dc)[i];
            float* dst = sK + row * SK_P + c4 * 4;
            dst[0] = to_tf32(v.x); dst[1] = to_tf32(v.y);
            dst[2] = to_tf32(v.z); dst[3] = to_tf32(v.w);
        }
        __syncthreads();

        float c[2][4] = {{0.f,0.f,0.f,0.f},{0.f,0.f,0.f,0.f}};
#pragma unroll
        for (int ks = 0; ks < 8; ks++) {
#pragma unroll
            for (int nt = 0; nt < 2; nt++) {
                const float* bp = sK + (kq + nt * 8 + gid) * SK_P + ks * 8 + tig;
                mma8(c[nt], aq[ks][0], aq[ks][1], aq[ks][2], aq[ks][3],
                     bp[0], bp[4]);
            }
        }
#pragma unroll
        for (int nt = 0; nt < 2; nt++) {
            int col = kt * KT + kq + nt * 8 + tig * 2;
            float* p  = sS + (qb + gid) * SS_P + col;
            float* p2 = p + 8 * SS_P;
            p[0]  = c[nt][0]; p[1]  = c[nt][1];
            p2[0] = c[nt][2]; p2[1] = c[nt][3];
        }
    }
    __syncthreads();

    // ---------------- softmax + post-softmax mask + attn write ----------------
#pragma unroll
    for (int r = 0; r < 4; r++) {          // each warp owns 4 rows
        int row = warp * 4 + r;
        float* srow = sS + row * SS_P;
        float4* srow4 = reinterpret_cast<float4*>(srow);

        float mx = -3.0e38f;
#pragma unroll
        for (int i = 0; i < 8; i++) {
            float4 v = srow4[lane + i * 32];
            mx = fmaxf(mx, fmaxf(fmaxf(v.x, v.y), fmaxf(v.z, v.w)));
        }
#pragma unroll
        for (int o = 16; o > 0; o >>= 1)
            mx = fmaxf(mx, __shfl_xor_sync(0xffffffffu, mx, o));

        float sum = 0.f;
#pragma unroll
        for (int i = 0; i < 8; i++) {
            float4 v = srow4[lane + i * 32];
            v.x = __expf(v.x - mx); v.y = __expf(v.y - mx);
            v.z = __expf(v.z - mx); v.w = __expf(v.w - mx);
            srow4[lane + i * 32] = v;
            sum += (v.x + v.y) + (v.z + v.w);
        }
#pragma unroll
        for (int o = 16; o > 0; o >>= 1)
            sum += __shfl_xor_sync(0xffffffffu, sum, o);
        float inv = 1.0f / sum;

        const int4* mrow = reinterpret_cast<const int4*>(Mg + row * Sc);
        float4* arow = reinterpret_cast<float4*>(outA + (size_t)row * Sc);
#pragma unroll
        for (int i = 0; i < 8; i++) {
            int idx = lane + i * 32;
            float4 v = srow4[idx];
            int4 m = mrow[idx];
            float4 w;
            w.x = m.x ? v.x * inv : -100000.0f;
            w.y = m.y ? v.y * inv : -100000.0f;
            w.z = m.z ? v.z * inv : -100000.0f;
            w.w = m.w ? v.w * inv : -100000.0f;
            arow[idx] = w;                         // exact fp32 attn to gmem
            float4 t;                              // tf32 copy for GEMM2
            t.x = to_tf32(w.x); t.y = to_tf32(w.y);
            t.z = to_tf32(w.z); t.w = to_tf32(w.w);
            srow4[idx] = t;
        }
    }

    // ---------------- GEMM2: out = attn_masked @ V -----------------------------
    const int db = (warp & 3) << 4;        // d-quarter: 0,16,32,48
    float c2[2][4] = {{0.f,0.f,0.f,0.f},{0.f,0.f,0.f,0.f}};
    for (int vt = 0; vt < Sc / KT; vt++) {
        __syncthreads();   // also orders softmax writes before first reads
        for (int i = tid; i < KT * Dc / 4; i += NT) {
            int row = i >> 4, c4 = i & 15;
            float4 v = reinterpret_cast<const float4*>(Vg + vt * KT * Dc)[i];
            float* dst = sV + row * SV_P + c4 * 4;
            dst[0] = to_tf32(v.x); dst[1] = to_tf32(v.y);
            dst[2] = to_tf32(v.z); dst[3] = to_tf32(v.w);
        }
        __syncthreads();
#pragma unroll
        for (int ks = 0; ks < 8; ks++) {
            const float* ap = sS + (qb + gid) * SS_P + vt * KT + ks * 8 + tig;
            float a0 = ap[0];
            float a1 = ap[8 * SS_P];
            float a2 = ap[4];
            float a3 = ap[8 * SS_P + 4];
#pragma unroll
            for (int nt = 0; nt < 2; nt++) {
                const float* bp = sV + (ks * 8 + tig) * SV_P + db + nt * 8 + gid;
                mma8(c2[nt], a0, a1, a2, a3, bp[0], bp[4 * SV_P]);
            }
        }
    }

#pragma unroll
    for (int nt = 0; nt < 2; nt++) {
        int col = db + nt * 8 + tig * 2;
        float* p  = outO + (qb + gid) * Dc + col;
        float* p2 = outO + (qb + gid + 8) * Dc + col;
        p[0]  = c2[nt][0]; p[1]  = c2[nt][1];
        p2[0] = c2[nt][2]; p2[1] = c2[nt][3];
    }
}

extern "C" void kernel_launch(void* const* d_in, const int* in_sizes, int n_in,
                              void* d_out, int out_size)
{
    (void)in_sizes; (void)n_in; (void)out_size;
    const float* Q = (const float*)d_in[0];
    const float* K = (const float*)d_in[1];
    const float* V = (const float*)d_in[2];
    const int*   M = (const int*)d_in[3];
    float* out = (float*)d_out;

    cudaFuncSetAttribute(attn_tf32_kernel,
                         cudaFuncAttributeMaxDynamicSharedMemorySize,
                         SMEM_FLOATS * (int)sizeof(float));
    dim3 grid(Sc / TQ, BH);
    attn_tf32_kernel<<<grid, NT, SMEM_FLOATS * sizeof(float)>>>(Q, K, V, M, out);
}

// round 2
// speedup vs baseline: 2.5183x; 2.5183x over previous
#include <cuda_runtime.h>
#include <cstdint>

namespace {
constexpr int Bc = 8, Hc = 16, Sc = 1024, Dc = 64;
constexpr int BH = Bc * Hc;
constexpr int TQ = 16;            // q rows per CTA
constexpr int NT = 256;           // threads per CTA (8 warps)
constexpr int KT = 64;            // k tile
// smem pitches (floats), chosen for conflict-free mma fragment LDS
constexpr int SQ_P = 68;
constexpr int SK_P = 68;          // K stored [kcol][kdim]
constexpr int SV_P = 72;          // V stored [k][d]
constexpr int SS_P = 1028;
constexpr int BUFSZ = KT * SV_P;  // 4608 floats, holds K (64x68) or V (64x72)
constexpr int SMEM_FLOATS = TQ * SS_P + TQ * SQ_P + 2 * BUFSZ;  // 26752
constexpr size_t ATTN_OFF = (size_t)BH * Sc * Dc;   // out first, then attn
}

__device__ __forceinline__ float to_tf32(float x) {
    uint32_t u;
    asm("cvt.rna.tf32.f32 %0, %1;" : "=r"(u) : "f"(x));
    return __uint_as_float(u);
}

__device__ __forceinline__ void mma8(float c[4],
                                     float a0, float a1, float a2, float a3,
                                     float b0, float b1) {
    asm volatile(
        "mma.sync.aligned.m16n8k8.row.col.f32.tf32.tf32.f32 "
        "{%0,%1,%2,%3}, {%4,%5,%6,%7}, {%8,%9}, {%0,%1,%2,%3};\n"
        : "+f"(c[0]), "+f"(c[1]), "+f"(c[2]), "+f"(c[3])
        : "r"(__float_as_uint(a0)), "r"(__float_as_uint(a1)),
          "r"(__float_as_uint(a2)), "r"(__float_as_uint(a3)),
          "r"(__float_as_uint(b0)), "r"(__float_as_uint(b1)));
}

// cvt-to-tf32 + store a 64x64 tile (held in 4 float4 regs/thread) into smem.
__device__ __forceinline__ void cvt_sts_tile(float* dst, int pitch,
                                             const float4* r, int tid) {
#pragma unroll
    for (int j = 0; j < 4; j++) {
        int i = tid + j * NT;          // float4 index within 64x64 tile
        int row = i >> 4, c4 = i & 15;
        float4 t;
        t.x = to_tf32(r[j].x); t.y = to_tf32(r[j].y);
        t.z = to_tf32(r[j].z); t.w = to_tf32(r[j].w);
        *reinterpret_cast<float4*>(dst + row * pitch + c4 * 4) = t;
    }
}

__global__ void __launch_bounds__(NT, 2)
attn_tf32_kernel(const float* __restrict__ Qg_, const float* __restrict__ Kg_,
                 const float* __restrict__ Vg_, const int* __restrict__ Mg_,
                 float* __restrict__ out)
{
    extern __shared__ float sm[];
    float* sS  = sm;                      // [TQ][SS_P]
    float* sQ  = sS + TQ * SS_P;          // [TQ][SQ_P]
    float* sKV = sQ + TQ * SQ_P;          // [2][BUFSZ] double buffer (K or V)

    const int qt   = blockIdx.x;          // 0..63
    const int bh   = blockIdx.y;          // 0..127
    const int b    = bh >> 4;
    const int tid  = threadIdx.x;
    const int warp = tid >> 5;            // 0..7
    const int lane = tid & 31;
    const int gid  = lane >> 2;           // 0..7
    const int tig  = lane & 3;            // 0..3
    const int w8   = warp << 3;           // warp's n-block

    const float* Qg = Qg_ + ((size_t)bh * Sc + (size_t)qt * TQ) * Dc;
    const float* Kg = Kg_ + (size_t)bh * Sc * Dc;
    const float* Vg = Vg_ + (size_t)bh * Sc * Dc;
    float* outO = out + ((size_t)bh * Sc + (size_t)qt * TQ) * Dc;
    float* outA = out + ATTN_OFF + ((size_t)bh * Sc + (size_t)qt * TQ) * Sc;
    const int* Mg = Mg_ + ((size_t)b * Sc + (size_t)qt * TQ) * Sc;

    // ---------------- load Q tile: scale by 1/8, round to tf32 ---------------
    {
        int i = tid;                       // TQ*Dc/4 = 256 float4s, one each
        int row = i >> 4, c4 = i & 15;
        float4 v = reinterpret_cast<const float4*>(Qg)[i];
        float* dst = sQ + row * SQ_P + c4 * 4;
        dst[0] = to_tf32(v.x * 0.125f);
        dst[1] = to_tf32(v.y * 0.125f);
        dst[2] = to_tf32(v.z * 0.125f);
        dst[3] = to_tf32(v.w * 0.125f);
    }
    __syncthreads();

    // Preload A fragments (Q) once: reused across all 16 K tiles.
    float aq[8][4];
#pragma unroll
    for (int ks = 0; ks < 8; ks++) {
        const float* p = sQ + gid * SQ_P + ks * 8 + tig;
        aq[ks][0] = p[0];
        aq[ks][1] = p[8 * SQ_P];
        aq[ks][2] = p[4];
        aq[ks][3] = p[8 * SQ_P + 4];
    }

    // ---------------- GEMM1: scores = (Q/8) @ K^T, pipelined -----------------
    {
        float4 r[4];
        const float4* K0 = reinterpret_cast<const float4*>(Kg);
#pragma unroll
        for (int j = 0; j < 4; j++) r[j] = K0[tid + j * NT];
        cvt_sts_tile(sKV, SK_P, r, tid);
        __syncthreads();

        for (int kt = 0; kt < Sc / KT; kt++) {
            const float* kbuf = sKV + (kt & 1) * BUFSZ;
            if (kt < 15) {
                const float4* Kn =
                    reinterpret_cast<const float4*>(Kg + (size_t)(kt + 1) * KT * Dc);
#pragma unroll
                for (int j = 0; j < 4; j++) r[j] = Kn[tid + j * NT];
            }

            float cA[4] = {0.f, 0.f, 0.f, 0.f};
            float cB[4] = {0.f, 0.f, 0.f, 0.f};
#pragma unroll
            for (int ks = 0; ks < 8; ks += 2) {
                const float* bp0 = kbuf + (w8 + gid) * SK_P + ks * 8 + tig;
                mma8(cA, aq[ks][0], aq[ks][1], aq[ks][2], aq[ks][3],
                     bp0[0], bp0[4]);
                const float* bp1 = bp0 + 8;
                mma8(cB, aq[ks + 1][0], aq[ks + 1][1], aq[ks + 1][2], aq[ks + 1][3],
                     bp1[0], bp1[4]);
            }
            int col = kt * KT + w8 + tig * 2;
            float* p  = sS + gid * SS_P + col;
            float* p2 = p + 8 * SS_P;
            p[0]  = cA[0] + cB[0]; p[1]  = cA[1] + cB[1];
            p2[0] = cA[2] + cB[2]; p2[1] = cA[3] + cB[3];

            if (kt < 15)
                cvt_sts_tile(sKV + ((kt + 1) & 1) * BUFSZ, SK_P, r, tid);
            __syncthreads();
        }
    }

    // Prefetch V tile 0 (hides gmem latency under softmax)
    float4 rv[4];
    {
        const float4* V0 = reinterpret_cast<const float4*>(Vg);
#pragma unroll
        for (int j = 0; j < 4; j++) rv[j] = V0[tid + j * NT];
    }

    // ---------------- softmax + post-softmax mask + attn write ---------------
#pragma unroll
    for (int rr = 0; rr < 2; rr++) {      // each warp owns 2 rows
        int row = warp * 2 + rr;
        float* srow = sS + row * SS_P;
        float4* srow4 = reinterpret_cast<float4*>(srow);

        float mx = -3.0e38f;
#pragma unroll
        for (int i = 0; i < 8; i++) {
            float4 v = srow4[lane + i * 32];
            mx = fmaxf(mx, fmaxf(fmaxf(v.x, v.y), fmaxf(v.z, v.w)));
        }
#pragma unroll
        for (int o = 16; o > 0; o >>= 1)
            mx = fmaxf(mx, __shfl_xor_sync(0xffffffffu, mx, o));

        float sum = 0.f;
#pragma unroll
        for (int i = 0; i < 8; i++) {
            float4 v = srow4[lane + i * 32];
            v.x = __expf(v.x - mx); v.y = __expf(v.y - mx);
            v.z = __expf(v.z - mx); v.w = __expf(v.w - mx);
            srow4[lane + i * 32] = v;
            sum += (v.x + v.y) + (v.z + v.w);
        }
#pragma unroll
        for (int o = 16; o > 0; o >>= 1)
            sum += __shfl_xor_sync(0xffffffffu, sum, o);
        float inv = 1.0f / sum;

        const int4* mrow = reinterpret_cast<const int4*>(Mg + (size_t)row * Sc);
        float4* arow = reinterpret_cast<float4*>(outA + (size_t)row * Sc);
#pragma unroll
        for (int i = 0; i < 8; i++) {
            int idx = lane + i * 32;
            float4 v = srow4[idx];
            int4 m = mrow[idx];
            float4 w;
            w.x = m.x ? v.x * inv : -100000.0f;
            w.y = m.y ? v.y * inv : -100000.0f;
            w.z = m.z ? v.z * inv : -100000.0f;
            w.w = m.w ? v.w * inv : -100000.0f;
            __stcs(&arow[idx], w);                 // exact fp32 attn, streaming
            float4 t;                              // tf32 copy for GEMM2
            t.x = to_tf32(w.x); t.y = to_tf32(w.y);
            t.z = to_tf32(w.z); t.w = to_tf32(w.w);
            srow4[idx] = t;
        }
    }

    // ---------------- GEMM2: out = attn_masked @ V, pipelined ----------------
    cvt_sts_tile(sKV, SV_P, rv, tid);     // V tile 0 -> buf 0
    __syncthreads();                       // covers softmax sS writes too

    float c2A[4] = {0.f, 0.f, 0.f, 0.f};
    float c2B[4] = {0.f, 0.f, 0.f, 0.f};
    for (int vt = 0; vt < Sc / KT; vt++) {
        const float* vbuf = sKV + (vt & 1) * BUFSZ;
        if (vt < 15) {
            const float4* Vn =
                reinterpret_cast<const float4*>(Vg + (size_t)(vt + 1) * KT * Dc);
#pragma unroll
            for (int j = 0; j < 4; j++) rv[j] = Vn[tid + j * NT];
        }
#pragma unroll
        for (int ks = 0; ks < 8; ks += 2) {
            const float* ap0 = sS + gid * SS_P + vt * KT + ks * 8 + tig;
            float a00 = ap0[0];
            float a01 = ap0[8 * SS_P];
            float a02 = ap0[4];
            float a03 = ap0[8 * SS_P + 4];
            const float* bp0 = vbuf + (ks * 8 + tig) * SV_P + w8 + gid;
            mma8(c2A, a00, a01, a02, a03, bp0[0], bp0[4 * SV_P]);

            const float* ap1 = ap0 + 8;
            float a10 = ap1[0];
            float a11 = ap1[8 * SS_P];
            float a12 = ap1[4];
            float a13 = ap1[8 * SS_P + 4];
            const float* bp1 = vbuf + ((ks + 1) * 8 + tig) * SV_P + w8 + gid;
            mma8(c2B, a10, a11, a12, a13, bp1[0], bp1[4 * SV_P]);
        }
        if (vt < 15)
            cvt_sts_tile(sKV + ((vt + 1) & 1) * BUFSZ, SV_P, rv, tid);
        __syncthreads();
    }

    {
        int col = w8 + tig * 2;
        float* p  = outO + gid * Dc + col;
        float* p2 = outO + (gid + 8) * Dc + col;
        p[0]  = c2A[0] + c2B[0]; p[1]  = c2A[1] + c2B[1];
        p2[0] = c2A[2] + c2B[2]; p2[1] = c2A[3] + c2B[3];
    }
}

extern "C" void kernel_launch(void* const* d_in, const int* in_sizes, int n_in,
                              void* d_out, int out_size)
{
    (void)in_sizes; (void)n_in; (void)out_size;
    const float* Q = (const float*)d_in[0];
    const float* K = (const float*)d_in[1];
    const float* V = (const float*)d_in[2];
    const int*   M = (const int*)d_in[3];
    float* out = (float*)d_out;

    cudaFuncSetAttribute(attn_tf32_kernel,
                         cudaFuncAttributeMaxDynamicSharedMemorySize,
                         SMEM_FLOATS * (int)sizeof(float));
    dim3 grid(Sc / TQ, BH);
    attn_tf32_kernel<<<grid, NT, SMEM_FLOATS * sizeof(float)>>>(Q, K, V, M, out);
}